// round 13
// baseline (speedup 1.0000x reference)
#include <cuda_runtime.h>
#include <cuda_fp16.h>
#include <cstdint>

#define BATCH   8192
#define CLASSES 10000
#define C4      2500                    // float4 per row
#define TROWS   2                       // rows per tile
#define NTILES  (BATCH / TROWS)         // 4096
#define THREADS 1024
#define MAXGRID 160
#define NREP    8
#define TILE_BYTES (TROWS * CLASSES * 4)     // 80000 raw fp32 per tile
#define STAGE_OFF  (2 * TILE_BYTES)          // fp16 stage after the 2-buffer ring
#define SMEM_DYN   (2 * TILE_BYTES + TROWS * CLASSES * 2)   // 200000 B

// zero-initialized at module load; the last block consume-and-clears all of
// these each call, so the invariant "zeroed at kernel entry" holds on every
// graph replay.
__device__ float        g_rep[NREP][CLASSES];
__device__ float        g_counts[CLASSES];
__device__ unsigned int g_done;

// ---------------------------------------------------------------- helpers
__device__ __forceinline__ uint32_t s2u(const void* p) {
    uint32_t a;
    asm("{ .reg .u64 t; cvta.to.shared.u64 t, %1; cvt.u32.u64 %0, t; }"
        : "=r"(a) : "l"(p));
    return a;
}

__device__ __forceinline__ void mbar_init(uint32_t mb, uint32_t cnt) {
    asm volatile("mbarrier.init.shared.b64 [%0], %1;" :: "r"(mb), "r"(cnt) : "memory");
}

__device__ __forceinline__ void mbar_wait(uint32_t mb, uint32_t parity) {
    asm volatile(
        "{\n\t"
        ".reg .pred P;\n\t"
        "WL_%=: mbarrier.try_wait.parity.acquire.cta.shared::cta.b64 P, [%0], %1, 0x989680;\n\t"
        "@P bra.uni WD_%=;\n\t"
        "bra.uni WL_%=;\n\t"
        "WD_%=:\n\t"
        "}" :: "r"(mb), "r"(parity) : "memory");
}

// one elected thread: expect_tx + 4 bulk-async 20000B copies (one tile)
__device__ __forceinline__ void issue_tile(const float* __restrict__ x,
                                           char* dyn, uint32_t mb,
                                           int buf, long long tile) {
    asm volatile("mbarrier.arrive.expect_tx.shared.b64 _, [%0], %1;"
                 :: "r"(mb), "r"((uint32_t)TILE_BYTES) : "memory");
    const char* src = (const char*)x + (size_t)tile * TILE_BYTES;
    uint32_t dst = s2u(dyn + buf * TILE_BYTES);
    #pragma unroll
    for (int c = 0; c < 4; c++) {
        asm volatile(
            "cp.async.bulk.shared::cta.global.mbarrier::complete_tx::bytes "
            "[%0], [%1], %2, [%3];"
            :: "r"(dst + c * 20000), "l"(src + (size_t)c * 20000),
               "r"(20000u), "r"(mb) : "memory");
    }
}

// ---------------------------------------------------------------- single fused kernel
// 1 persistent CTA/SM, 1024 threads, double-buffered cp.async.bulk mainloop
// (unchanged from R12 — measured at the LTS cap). Histogram runs in blocks
// 0..7 overlapped with the mainloop. After the v4-RED flush, a threadfence-
// reduction elects the last block to produce the final scalar and clear all
// device state for the next graph replay.
__global__ __launch_bounds__(THREADS, 1) void k_main(const float* __restrict__ x,
                                                     const int* __restrict__ tgt,
                                                     float* __restrict__ out,
                                                     int grid) {
    extern __shared__ char dyn[];
    __shared__ float    wred[32];
    __shared__ float    inv[TROWS];
    __shared__ uint64_t mbar[2];
    __shared__ int      is_last;

    const int tid = threadIdx.x;
    const int bid = blockIdx.x;

    const uint32_t mb0 = s2u(&mbar[0]);
    const uint32_t mb1 = s2u(&mbar[1]);
    if (tid == 0) { mbar_init(mb0, 1); mbar_init(mb1, 1); }
    __syncthreads();

    const int n = (NTILES - 1 - bid) / grid + 1;   // tiles owned by this CTA
    if (tid == 0) {
        issue_tile(x, dyn, mb0, 0, bid);
        if (n > 1) issue_tile(x, dyn, mb1, 1, bid + (long long)grid);
    }

    // histogram side-job (blocks 0..7, 1024 targets each), overlapped with
    // the TMA-fed mainloop. Dtype-robust: detect int64-LE (odd int32 words
    // zero for values < 2^32) vs int32.
    if (bid < 8) {
        bool is64 = true;
        #pragma unroll
        for (int j = 1; j < 16; j += 2) is64 = is64 && (tgt[j] == 0);
        int i = bid * 1024 + tid;
        int t = is64 ? tgt[2 * i] : tgt[i];
        if (t >= 0 && t < CLASSES) atomicAdd(&g_counts[t], 1.0f);
    }

    float acc[3][4];
    #pragma unroll
    for (int k = 0; k < 3; k++)
        acc[k][0] = acc[k][1] = acc[k][2] = acc[k][3] = 0.0f;

    const int r = tid >> 9;          // 0..1 (512 threads per row)
    const int l = tid & 511;
    int ph0 = 0, ph1 = 0;

    for (int i = 0; i < n; i++) {
        const int buf = i & 1;
        const uint32_t mb = buf ? mb1 : mb0;
        mbar_wait(mb, buf ? ph1 : ph0);
        if (buf) ph1 ^= 1; else ph0 ^= 1;

        // ---- rowsum pass: raw fp32 from SMEM -> exp -> fp16 stage + sum
        const float4* raw4 = reinterpret_cast<const float4*>(dyn + buf * TILE_BYTES) + r * C4;
        uint2*        st   = reinterpret_cast<uint2*>(dyn + STAGE_OFF) + r * C4;

        float s = 0.0f;
        #pragma unroll
        for (int k = 0; k < 5; k++) {
            int j = l + 512 * k;
            if (j < C4) {
                float4 v = raw4[j];
                float e0 = __expf(v.x), e1 = __expf(v.y);
                float e2 = __expf(v.z), e3 = __expf(v.w);
                s += (e0 + e1) + (e2 + e3);
                __half2 h01 = __floats2half2_rn(e0, e1);
                __half2 h23 = __floats2half2_rn(e2, e3);
                st[j] = make_uint2(*reinterpret_cast<unsigned*>(&h01),
                                   *reinterpret_cast<unsigned*>(&h23));
            }
        }
        #pragma unroll
        for (int o = 16; o; o >>= 1) s += __shfl_down_sync(0xffffffffu, s, o);
        if ((tid & 31) == 0) wred[tid >> 5] = s;
        __syncthreads();                       // raw reads + wred/stage writes done

        // re-arm this buffer for tile i+2 while everyone else proceeds
        if (tid == 0 && i + 2 < n)
            issue_tile(x, dyn, mb, buf, bid + (long long)(i + 2) * grid);

        if (tid < TROWS) {
            float t = 0.0f;
            #pragma unroll
            for (int w = 0; w < 16; w++) t += wred[tid * 16 + w];
            inv[tid] = 1.0f / t;
        }
        __syncthreads();
        const float i0 = inv[0], i1 = inv[1];

        // ---- phase B: accumulate fixed classes into registers
        const uint2* st2 = reinterpret_cast<const uint2*>(dyn + STAGE_OFF);
        #pragma unroll
        for (int k = 0; k < 3; k++) {
            int j = tid + 1024 * k;
            if (j < C4) {
                uint2 u0 = st2[j], u1 = st2[C4 + j];
                float2 a = __half22float2(*reinterpret_cast<__half2*>(&u0.x));
                float2 b = __half22float2(*reinterpret_cast<__half2*>(&u0.y));
                float2 c = __half22float2(*reinterpret_cast<__half2*>(&u1.x));
                float2 d = __half22float2(*reinterpret_cast<__half2*>(&u1.y));
                acc[k][0] += a.x * i0 + c.x * i1;
                acc[k][1] += a.y * i0 + c.y * i1;
                acc[k][2] += b.x * i0 + d.x * i1;
                acc[k][3] += b.y * i0 + d.y * i1;
            }
        }
        __syncthreads();   // stage + wred reuse protection for next tile
    }

    // flush: vector-RED into one of 8 replica arrays (16B-aligned rows)
    float* rep = g_rep[bid & (NREP - 1)];
    #pragma unroll
    for (int k = 0; k < 3; k++) {
        int j = tid + 1024 * k;
        if (j < C4) {
            float* p = rep + 4 * j;
            asm volatile("red.global.add.v4.f32 [%0], {%1, %2, %3, %4};"
                         :: "l"(p), "f"(acc[k][0]), "f"(acc[k][1]),
                            "f"(acc[k][2]), "f"(acc[k][3]) : "memory");
        }
    }

    // ---- threadfence reduction: last block finishes the job
    __syncthreads();                 // all REDs of this block issued
    if (tid == 0) {
        __threadfence();             // make REDs + hist atomics globally visible
        unsigned int ticket = atomicAdd(&g_done, 1u);
        is_last = (ticket == (unsigned int)(grid - 1));
    }
    __syncthreads();

    if (is_last) {
        __threadfence();             // acquire: see every other block's writes
        float s = 0.0f;
        for (int c = tid; c < CLASSES; c += THREADS) {
            float v = 0.0f;
            #pragma unroll
            for (int p = 0; p < NREP; p++) { v += g_rep[p][c]; g_rep[p][c] = 0.0f; }
            v -= g_counts[c];
            g_counts[c] = 0.0f;      // consume-and-clear for next replay
            s += fabsf(v) * (1.0f / (float)BATCH);
        }
        __shared__ float sm[32];
        #pragma unroll
        for (int o = 16; o; o >>= 1) s += __shfl_down_sync(0xffffffffu, s, o);
        if ((tid & 31) == 0) sm[tid >> 5] = s;
        __syncthreads();
        if (tid < 32) {
            float t = sm[tid];
            #pragma unroll
            for (int o = 16; o; o >>= 1) t += __shfl_down_sync(0xffffffffu, t, o);
            if (tid == 0) {
                out[0] = t / (float)CLASSES;
                g_done = 0;          // reset for next replay
            }
        }
    }
}

// ---------------------------------------------------------------- launch
extern "C" void kernel_launch(void* const* d_in, const int* in_sizes, int n_in,
                              void* d_out, int out_size) {
    const float* x   = (const float*)d_in[0];   // [8192, 10000] fp32
    const int*   tgt = (const int*)d_in[1];     // [8192] int32 or int64 (detected)
    float*       out = (float*)d_out;

    int sms = 0;
    cudaDeviceGetAttribute(&sms, cudaDevAttrMultiProcessorCount, 0);
    int grid = sms;                              // 1 persistent CTA per SM
    if (grid < 9)       grid = 9;                // histogram needs blocks 0..7
    if (grid > MAXGRID) grid = MAXGRID;

    cudaFuncSetAttribute(k_main, cudaFuncAttributeMaxDynamicSharedMemorySize,
                         SMEM_DYN);

    k_main<<<grid, THREADS, SMEM_DYN>>>(x, tgt, out, grid);
}

// round 14
// speedup vs baseline: 1.1735x; 1.1735x over previous
#include <cuda_runtime.h>
#include <cuda_fp16.h>
#include <cstdint>

#define BATCH   8192
#define CLASSES 10000
#define C4      2500                    // float4 per row
#define TROWS   2                       // rows per tile
#define NTILES  (BATCH / TROWS)         // 4096
#define THREADS 1024
#define MAXGRID 160
#define NREP    8
#define TILE_BYTES (TROWS * CLASSES * 4)     // 80000 raw fp32 per tile
#define STAGE_OFF  (2 * TILE_BYTES)          // fp16 stage after the 2-buffer ring
#define SMEM_DYN   (2 * TILE_BYTES + TROWS * CLASSES * 2)   // 200000 B

// zero-initialized at module load; k_fin consume-and-clears after each use,
// so the invariant "zeroed at kernel_launch entry" holds on every replay.
__device__ float g_rep[NREP][CLASSES];
__device__ float g_counts[CLASSES];

// ---------------------------------------------------------------- helpers
__device__ __forceinline__ uint32_t s2u(const void* p) {
    uint32_t a;
    asm("{ .reg .u64 t; cvta.to.shared.u64 t, %1; cvt.u32.u64 %0, t; }"
        : "=r"(a) : "l"(p));
    return a;
}

__device__ __forceinline__ void mbar_init(uint32_t mb, uint32_t cnt) {
    asm volatile("mbarrier.init.shared.b64 [%0], %1;" :: "r"(mb), "r"(cnt) : "memory");
}

__device__ __forceinline__ void mbar_wait(uint32_t mb, uint32_t parity) {
    asm volatile(
        "{\n\t"
        ".reg .pred P;\n\t"
        "WL_%=: mbarrier.try_wait.parity.acquire.cta.shared::cta.b64 P, [%0], %1, 0x989680;\n\t"
        "@P bra.uni WD_%=;\n\t"
        "bra.uni WL_%=;\n\t"
        "WD_%=:\n\t"
        "}" :: "r"(mb), "r"(parity) : "memory");
}

// one elected thread: expect_tx + 4 bulk-async 20000B copies (one tile)
__device__ __forceinline__ void issue_tile(const float* __restrict__ x,
                                           char* dyn, uint32_t mb,
                                           int buf, long long tile) {
    asm volatile("mbarrier.arrive.expect_tx.shared.b64 _, [%0], %1;"
                 :: "r"(mb), "r"((uint32_t)TILE_BYTES) : "memory");
    const char* src = (const char*)x + (size_t)tile * TILE_BYTES;
    uint32_t dst = s2u(dyn + buf * TILE_BYTES);
    #pragma unroll
    for (int c = 0; c < 4; c++) {
        asm volatile(
            "cp.async.bulk.shared::cta.global.mbarrier::complete_tx::bytes "
            "[%0], [%1], %2, [%3];"
            :: "r"(dst + c * 20000), "l"(src + (size_t)c * 20000),
               "r"(20000u), "r"(mb) : "memory");
    }
}

// ---------------------------------------------------------------- persistent main
// 1 CTA/SM, 1024 threads, double-buffered cp.async.bulk (== R12's measured
// 6.4 TB/s mainloop). Histogram runs in blocks 0..7 overlapped with the
// mainloop. Flush = red.global.add.v4 into one of 8 replica arrays. No
// in-kernel tail (the threadfence-reduction tail measured +17us in R13).
__global__ __launch_bounds__(THREADS, 1) void k_main(const float* __restrict__ x,
                                                     const int* __restrict__ tgt,
                                                     float* __restrict__ out,
                                                     int grid) {
    extern __shared__ char dyn[];
    __shared__ float    wred[32];
    __shared__ float    inv[TROWS];
    __shared__ uint64_t mbar[2];

    const int tid = threadIdx.x;
    const int bid = blockIdx.x;
    if (bid == 0 && tid == 0) out[0] = 0.0f;   // ordered before k_fin (stream)

    const uint32_t mb0 = s2u(&mbar[0]);
    const uint32_t mb1 = s2u(&mbar[1]);
    if (tid == 0) { mbar_init(mb0, 1); mbar_init(mb1, 1); }
    __syncthreads();

    const int n = (NTILES - 1 - bid) / grid + 1;   // tiles owned by this CTA
    if (tid == 0) {
        issue_tile(x, dyn, mb0, 0, bid);
        if (n > 1) issue_tile(x, dyn, mb1, 1, bid + (long long)grid);
    }

    // histogram side-job (blocks 0..7, 1024 targets each), overlapped with
    // the TMA-fed mainloop. Dtype-robust: detect int64-LE (odd int32 words
    // zero for values < 2^32) vs int32.
    if (bid < 8) {
        bool is64 = true;
        #pragma unroll
        for (int j = 1; j < 16; j += 2) is64 = is64 && (tgt[j] == 0);
        int i = bid * 1024 + tid;
        int t = is64 ? tgt[2 * i] : tgt[i];
        if (t >= 0 && t < CLASSES) atomicAdd(&g_counts[t], 1.0f);
    }

    float acc[3][4];
    #pragma unroll
    for (int k = 0; k < 3; k++)
        acc[k][0] = acc[k][1] = acc[k][2] = acc[k][3] = 0.0f;

    const int r = tid >> 9;          // 0..1 (512 threads per row)
    const int l = tid & 511;
    int ph0 = 0, ph1 = 0;

    for (int i = 0; i < n; i++) {
        const int buf = i & 1;
        const uint32_t mb = buf ? mb1 : mb0;
        mbar_wait(mb, buf ? ph1 : ph0);
        if (buf) ph1 ^= 1; else ph0 ^= 1;

        // ---- rowsum pass: raw fp32 from SMEM -> exp -> fp16 stage + sum
        const float4* raw4 = reinterpret_cast<const float4*>(dyn + buf * TILE_BYTES) + r * C4;
        uint2*        st   = reinterpret_cast<uint2*>(dyn + STAGE_OFF) + r * C4;

        float s = 0.0f;
        #pragma unroll
        for (int k = 0; k < 5; k++) {
            int j = l + 512 * k;
            if (j < C4) {
                float4 v = raw4[j];
                float e0 = __expf(v.x), e1 = __expf(v.y);
                float e2 = __expf(v.z), e3 = __expf(v.w);
                s += (e0 + e1) + (e2 + e3);
                __half2 h01 = __floats2half2_rn(e0, e1);
                __half2 h23 = __floats2half2_rn(e2, e3);
                st[j] = make_uint2(*reinterpret_cast<unsigned*>(&h01),
                                   *reinterpret_cast<unsigned*>(&h23));
            }
        }
        #pragma unroll
        for (int o = 16; o; o >>= 1) s += __shfl_down_sync(0xffffffffu, s, o);
        if ((tid & 31) == 0) wred[tid >> 5] = s;
        __syncthreads();                       // raw reads + wred/stage writes done

        // re-arm this buffer for tile i+2 while everyone else proceeds
        if (tid == 0 && i + 2 < n)
            issue_tile(x, dyn, mb, buf, bid + (long long)(i + 2) * grid);

        if (tid < TROWS) {
            float t = 0.0f;
            #pragma unroll
            for (int w = 0; w < 16; w++) t += wred[tid * 16 + w];
            inv[tid] = 1.0f / t;
        }
        __syncthreads();
        const float i0 = inv[0], i1 = inv[1];

        // ---- phase B: accumulate fixed classes into registers
        const uint2* st2 = reinterpret_cast<const uint2*>(dyn + STAGE_OFF);
        #pragma unroll
        for (int k = 0; k < 3; k++) {
            int j = tid + 1024 * k;
            if (j < C4) {
                uint2 u0 = st2[j], u1 = st2[C4 + j];
                float2 a = __half22float2(*reinterpret_cast<__half2*>(&u0.x));
                float2 b = __half22float2(*reinterpret_cast<__half2*>(&u0.y));
                float2 c = __half22float2(*reinterpret_cast<__half2*>(&u1.x));
                float2 d = __half22float2(*reinterpret_cast<__half2*>(&u1.y));
                acc[k][0] += a.x * i0 + c.x * i1;
                acc[k][1] += a.y * i0 + c.y * i1;
                acc[k][2] += b.x * i0 + d.x * i1;
                acc[k][3] += b.y * i0 + d.y * i1;
            }
        }
        __syncthreads();   // stage + wred reuse protection for next tile
    }

    // flush: vector-RED into one of 8 replica arrays (16B-aligned rows),
    // fire-and-forget (kernel boundary provides the global visibility).
    float* rep = g_rep[bid & (NREP - 1)];
    #pragma unroll
    for (int k = 0; k < 3; k++) {
        int j = tid + 1024 * k;
        if (j < C4) {
            float* p = rep + 4 * j;
            asm volatile("red.global.add.v4.f32 [%0], {%1, %2, %3, %4};"
                         :: "l"(p), "f"(acc[k][0]), "f"(acc[k][1]),
                            "f"(acc[k][2]), "f"(acc[k][3]) : "memory");
        }
    }
}

// ---------------------------------------------------------------- tiny epilogue
// 40 blocks x 256 threads: <=1 class per thread. Read 8 L2-hot replicas +
// count, |conf - count|/B, consume-and-clear state for the next replay,
// block-reduce, one atomicAdd per block. No target rescan.
__global__ __launch_bounds__(256) void k_fin(float* __restrict__ out) {
    const int tid = threadIdx.x;
    const int c   = blockIdx.x * 256 + tid;

    float s = 0.0f;
    if (c < CLASSES) {
        float v = 0.0f;
        #pragma unroll
        for (int p = 0; p < NREP; p++) { v += g_rep[p][c]; g_rep[p][c] = 0.0f; }
        v -= g_counts[c];
        g_counts[c] = 0.0f;                  // clear for next replay
        s = fabsf(v) * (1.0f / (float)BATCH);
    }

    __shared__ float sm[8];
    #pragma unroll
    for (int o = 16; o; o >>= 1) s += __shfl_down_sync(0xffffffffu, s, o);
    if ((tid & 31) == 0) sm[tid >> 5] = s;
    __syncthreads();
    if (tid < 8) {
        float t = sm[tid];
        t += __shfl_down_sync(0xffu, t, 4);
        t += __shfl_down_sync(0xffu, t, 2);
        t += __shfl_down_sync(0xffu, t, 1);
        if (tid == 0) atomicAdd(out, t / (float)CLASSES);
    }
}

// ---------------------------------------------------------------- launch
extern "C" void kernel_launch(void* const* d_in, const int* in_sizes, int n_in,
                              void* d_out, int out_size) {
    const float* x   = (const float*)d_in[0];   // [8192, 10000] fp32
    const int*   tgt = (const int*)d_in[1];     // [8192] int32 or int64 (detected)
    float*       out = (float*)d_out;

    int sms = 0;
    cudaDeviceGetAttribute(&sms, cudaDevAttrMultiProcessorCount, 0);
    int grid = sms;                              // 1 persistent CTA per SM
    if (grid < 9)       grid = 9;                // histogram needs blocks 0..7
    if (grid > MAXGRID) grid = MAXGRID;

    cudaFuncSetAttribute(k_main, cudaFuncAttributeMaxDynamicSharedMemorySize,
                         SMEM_DYN);

    k_main<<<grid, THREADS, SMEM_DYN>>>(x, tgt, out, grid);
    k_fin<<<(CLASSES + 255) / 256, 256>>>(out);   // 40 blocks
}